// round 3
// baseline (speedup 1.0000x reference)
#include <cuda_runtime.h>

// Problem constants
#define TT 1024
#define BBATCH 4
#define EE 1024
#define HH 16
#define NBH 64              // B*H
#define MROWS 4096          // T*B
#define SCALE_Q 0.125f      // HD^-0.5, HD=64
#define SEG 4194304         // T*B*E elements per output segment

// ---------------- scratch (__device__ globals; no allocations) ----------------
__device__ float g_q[(size_t)NBH * TT * 128];      // [bh][t][ qr*s (64) | qi*s (64) ]
__device__ float g_k[(size_t)NBH * TT * 128];      // [bh][t][ kr+ki | kr-ki ]
__device__ float g_v[(size_t)NBH * TT * 128];      // [bh][t][ vr | vi ]
__device__ float g_aw[(size_t)NBH * TT * TT];      // raw awr, 256 MB
__device__ float g_attn_re[(size_t)MROWS * EE];    // attn real, (t*B+b, e)
__device__ float g_attn_im[(size_t)MROWS * EE];    // attn imag
__device__ float g_minmax[2];                      // [min, max]
__device__ float g_ms[2];                          // [min, 1/(max-min)]

// ---------------- helpers ----------------
__device__ __forceinline__ void atomicMinF(float* addr, float val) {
    int old = __float_as_int(*addr);
    while (val < __int_as_float(old)) {
        int assumed = old;
        old = atomicCAS((int*)addr, assumed, __float_as_int(val));
        if (old == assumed) break;
    }
}
__device__ __forceinline__ void atomicMaxF(float* addr, float val) {
    int old = __float_as_int(*addr);
    while (val > __int_as_float(old)) {
        int assumed = old;
        old = atomicCAS((int*)addr, assumed, __float_as_int(val));
        if (old == assumed) break;
    }
}

__global__ void k_init() {
    g_minmax[0] = __int_as_float(0x7f800000);   // +inf
    g_minmax[1] = __int_as_float(0xff800000);   // -inf
}

__global__ void k_scale() {
    float mn = g_minmax[0], mx = g_minmax[1];
    g_ms[0] = mn;
    g_ms[1] = 1.0f / (mx - mn);
}

// ---------------- K1: complex input projection ----------------
// C(4096,3072) = X(4096,1024) @ W(3072,1024)^T + b   (complex)
// Epilogue scatters into g_q / g_k / g_v packed layouts.
__global__ __launch_bounds__(256, 1) void k_proj(
    const float* __restrict__ xr, const float* __restrict__ xi,
    const float* __restrict__ wr, const float* __restrict__ wi,
    const float* __restrict__ br, const float* __restrict__ bi)
{
    __shared__ float Asr[8][128], Asi[8][128], Bsr[8][128], Bsi[8][128];
    const int tid = threadIdx.x;
    const int tx = tid & 15, ty = tid >> 4;
    const int bm = blockIdx.y * 128;
    const int bn = blockIdx.x * 128;
    const int lr = tid >> 1;
    const int lk = (tid & 1) * 4;

    float cr[8][8] = {}, ci[8][8] = {};

    const float* pxr = xr + (size_t)(bm + lr) * EE + lk;
    const float* pxi = xi + (size_t)(bm + lr) * EE + lk;
    const float* pwr = wr + (size_t)(bn + lr) * EE + lk;
    const float* pwi = wi + (size_t)(bn + lr) * EE + lk;

    for (int kt = 0; kt < EE; kt += 8) {
        float4 a0 = *(const float4*)(pxr + kt);
        float4 a1 = *(const float4*)(pxi + kt);
        float4 b0 = *(const float4*)(pwr + kt);
        float4 b1 = *(const float4*)(pwi + kt);
        __syncthreads();
        Asr[lk+0][lr]=a0.x; Asr[lk+1][lr]=a0.y; Asr[lk+2][lr]=a0.z; Asr[lk+3][lr]=a0.w;
        Asi[lk+0][lr]=a1.x; Asi[lk+1][lr]=a1.y; Asi[lk+2][lr]=a1.z; Asi[lk+3][lr]=a1.w;
        Bsr[lk+0][lr]=b0.x; Bsr[lk+1][lr]=b0.y; Bsr[lk+2][lr]=b0.z; Bsr[lk+3][lr]=b0.w;
        Bsi[lk+0][lr]=b1.x; Bsi[lk+1][lr]=b1.y; Bsi[lk+2][lr]=b1.z; Bsi[lk+3][lr]=b1.w;
        __syncthreads();
        #pragma unroll
        for (int k = 0; k < 8; k++) {
            float ar[8], ai[8], bre[8], bim[8];
            #pragma unroll
            for (int i = 0; i < 8; i++) { ar[i] = Asr[k][ty*8+i]; ai[i] = Asi[k][ty*8+i]; }
            #pragma unroll
            for (int j = 0; j < 8; j++) { bre[j] = Bsr[k][tx*8+j]; bim[j] = Bsi[k][tx*8+j]; }
            #pragma unroll
            for (int i = 0; i < 8; i++)
                #pragma unroll
                for (int j = 0; j < 8; j++) {
                    cr[i][j] += ar[i]*bre[j] - ai[i]*bim[j];
                    ci[i][j] += ar[i]*bim[j] + ai[i]*bre[j];
                }
        }
    }

    const int seg = bn >> 10;   // 0=q, 1=k, 2=v (block never straddles)
    #pragma unroll
    for (int i = 0; i < 8; i++) {
        int m = bm + ty*8 + i;
        int t = m >> 2, bb = m & 3;
        #pragma unroll
        for (int j = 0; j < 8; j++) {
            int n = bn + tx*8 + j;
            float vr = cr[i][j] + br[n];
            float vi = ci[i][j] + bi[n];
            int nn = n & 1023;
            int h = nn >> 6, hd = nn & 63;
            size_t base = ((size_t)(bb * HH + h) * TT + t) * 128;
            if (seg == 0)      { g_q[base + hd] = vr * SCALE_Q; g_q[base + 64 + hd] = vi * SCALE_Q; }
            else if (seg == 1) { g_k[base + hd] = vr + vi;      g_k[base + 64 + hd] = vr - vi; }
            else               { g_v[base + hd] = vr;           g_v[base + 64 + hd] = vi; }
        }
    }
}

// ---------------- K2: per-head QK^T (real, K=128) + global min/max ----------------
__global__ __launch_bounds__(256, 2) void k_qk()
{
    __shared__ float As[8][128], Bs[8][128];
    __shared__ float smn[8], smx[8];
    const int tid = threadIdx.x;
    const int tx = tid & 15, ty = tid >> 4;
    const int bh = blockIdx.z;
    const int bm = blockIdx.y * 128;
    const int bn = blockIdx.x * 128;
    const int lr = tid >> 1;
    const int lk = (tid & 1) * 4;

    const float* A  = g_q + (size_t)bh * TT * 128;
    const float* Bp = g_k + (size_t)bh * TT * 128;

    float c[8][8] = {};
    for (int kt = 0; kt < 128; kt += 8) {
        float4 a0 = *(const float4*)(A  + (size_t)(bm + lr) * 128 + kt + lk);
        float4 b0 = *(const float4*)(Bp + (size_t)(bn + lr) * 128 + kt + lk);
        __syncthreads();
        As[lk+0][lr]=a0.x; As[lk+1][lr]=a0.y; As[lk+2][lr]=a0.z; As[lk+3][lr]=a0.w;
        Bs[lk+0][lr]=b0.x; Bs[lk+1][lr]=b0.y; Bs[lk+2][lr]=b0.z; Bs[lk+3][lr]=b0.w;
        __syncthreads();
        #pragma unroll
        for (int k = 0; k < 8; k++) {
            float a[8], b[8];
            #pragma unroll
            for (int i = 0; i < 8; i++) a[i] = As[k][ty*8+i];
            #pragma unroll
            for (int j = 0; j < 8; j++) b[j] = Bs[k][tx*8+j];
            #pragma unroll
            for (int i = 0; i < 8; i++)
                #pragma unroll
                for (int j = 0; j < 8; j++)
                    c[i][j] += a[i] * b[j];
        }
    }

    float mn = __int_as_float(0x7f800000), mx = __int_as_float(0xff800000);
    float* C = g_aw + (size_t)bh * TT * TT;
    #pragma unroll
    for (int i = 0; i < 8; i++) {
        size_t row = (size_t)(bm + ty*8 + i) * TT + bn + tx*8;
        #pragma unroll
        for (int j = 0; j < 8; j++) {
            float v = c[i][j];
            C[row + j] = v;
            mn = fminf(mn, v); mx = fmaxf(mx, v);
        }
    }
    // block reduce min/max
    const int lane = tid & 31, wid = tid >> 5;
    #pragma unroll
    for (int off = 16; off; off >>= 1) {
        mn = fminf(mn, __shfl_down_sync(0xffffffffu, mn, off));
        mx = fmaxf(mx, __shfl_down_sync(0xffffffffu, mx, off));
    }
    if (lane == 0) { smn[wid] = mn; smx[wid] = mx; }
    __syncthreads();
    if (tid == 0) {
        #pragma unroll
        for (int w = 1; w < 8; w++) { mn = fminf(mn, smn[w]); mx = fmaxf(mx, smx[w]); }
        atomicMinF(&g_minmax[0], mn);
        atomicMaxF(&g_minmax[1], mx);
    }
}

// ---------------- K4: per-head attn = norm(awr) @ [vr|vi] ----------------
__global__ __launch_bounds__(256, 2) void k_av()
{
    __shared__ float As[8][128], Bs[8][128];
    const int tid = threadIdx.x;
    const int tx = tid & 15, ty = tid >> 4;
    const int bm = blockIdx.x * 128;
    const int bh = blockIdx.y;
    const float mn = g_ms[0], sc = g_ms[1];

    const float* A = g_aw + (size_t)bh * TT * TT;
    const float* V = g_v  + (size_t)bh * TT * 128;

    const int lr = tid >> 1, lk = (tid & 1) * 4;    // A tile loader
    const int vkr = tid >> 5, vn = (tid & 31) * 4;  // B tile loader (8x128, direct)

    float c[8][8] = {};
    for (int kt = 0; kt < TT; kt += 8) {
        float4 a0 = *(const float4*)(A + (size_t)(bm + lr) * TT + kt + lk);
        float4 b0 = *(const float4*)(V + (size_t)(kt + vkr) * 128 + vn);
        a0.x = (a0.x - mn) * sc; a0.y = (a0.y - mn) * sc;
        a0.z = (a0.z - mn) * sc; a0.w = (a0.w - mn) * sc;
        __syncthreads();
        As[lk+0][lr]=a0.x; As[lk+1][lr]=a0.y; As[lk+2][lr]=a0.z; As[lk+3][lr]=a0.w;
        *(float4*)&Bs[vkr][vn] = b0;
        __syncthreads();
        #pragma unroll
        for (int k = 0; k < 8; k++) {
            float a[8], b[8];
            #pragma unroll
            for (int i = 0; i < 8; i++) a[i] = As[k][ty*8+i];
            #pragma unroll
            for (int j = 0; j < 8; j++) b[j] = Bs[k][tx*8+j];
            #pragma unroll
            for (int i = 0; i < 8; i++)
                #pragma unroll
                for (int j = 0; j < 8; j++)
                    c[i][j] += a[i] * b[j];
        }
    }

    const int bb = bh >> 4, h = bh & 15;
    #pragma unroll
    for (int i = 0; i < 8; i++) {
        int q = bm + ty*8 + i;
        size_t m = (size_t)q * BBATCH + bb;
        #pragma unroll
        for (int j = 0; j < 8; j++) {
            int n = tx*8 + j;
            int e = h * 64 + (n & 63);
            if (n < 64) g_attn_re[m * EE + e] = c[i][j];
            else        g_attn_im[m * EE + e] = c[i][j];
        }
    }
}

// ---------------- K5: aw_avg = (mean_h awr_raw - min) * scale ----------------
__global__ void k_avg(float* __restrict__ out)
{
    size_t idx = (size_t)blockIdx.x * 256 + threadIdx.x;   // over 4*1024*1024
    int b = (int)(idx >> 20);
    size_t qk = idx & 0xFFFFFu;
    float s = 0.f;
    #pragma unroll
    for (int h = 0; h < HH; h++)
        s += g_aw[(((size_t)(b * HH + h)) << 20) + qk];
    out[idx] = (s * (1.0f / HH) - g_ms[0]) * g_ms[1];
}

// ---------------- K6: complex output projection ----------------
__global__ __launch_bounds__(256, 1) void k_oproj(
    const float* __restrict__ owr, const float* __restrict__ owi,
    const float* __restrict__ obr, const float* __restrict__ obi,
    float* __restrict__ outre, float* __restrict__ outim)
{
    __shared__ float Asr[8][128], Asi[8][128], Bsr[8][128], Bsi[8][128];
    const int tid = threadIdx.x;
    const int tx = tid & 15, ty = tid >> 4;
    const int bm = blockIdx.y * 128;
    const int bn = blockIdx.x * 128;
    const int lr = tid >> 1;
    const int lk = (tid & 1) * 4;

    float cr[8][8] = {}, ci[8][8] = {};

    const float* par = g_attn_re + (size_t)(bm + lr) * EE + lk;
    const float* pai = g_attn_im + (size_t)(bm + lr) * EE + lk;
    const float* pwr = owr + (size_t)(bn + lr) * EE + lk;
    const float* pwi = owi + (size_t)(bn + lr) * EE + lk;

    for (int kt = 0; kt < EE; kt += 8) {
        float4 a0 = *(const float4*)(par + kt);
        float4 a1 = *(const float4*)(pai + kt);
        float4 b0 = *(const float4*)(pwr + kt);
        float4 b1 = *(const float4*)(pwi + kt);
        __syncthreads();
        Asr[lk+0][lr]=a0.x; Asr[lk+1][lr]=a0.y; Asr[lk+2][lr]=a0.z; Asr[lk+3][lr]=a0.w;
        Asi[lk+0][lr]=a1.x; Asi[lk+1][lr]=a1.y; Asi[lk+2][lr]=a1.z; Asi[lk+3][lr]=a1.w;
        Bsr[lk+0][lr]=b0.x; Bsr[lk+1][lr]=b0.y; Bsr[lk+2][lr]=b0.z; Bsr[lk+3][lr]=b0.w;
        Bsi[lk+0][lr]=b1.x; Bsi[lk+1][lr]=b1.y; Bsi[lk+2][lr]=b1.z; Bsi[lk+3][lr]=b1.w;
        __syncthreads();
        #pragma unroll
        for (int k = 0; k < 8; k++) {
            float ar[8], ai[8], bre[8], bim[8];
            #pragma unroll
            for (int i = 0; i < 8; i++) { ar[i] = Asr[k][ty*8+i]; ai[i] = Asi[k][ty*8+i]; }
            #pragma unroll
            for (int j = 0; j < 8; j++) { bre[j] = Bsr[k][tx*8+j]; bim[j] = Bsi[k][tx*8+j]; }
            #pragma unroll
            for (int i = 0; i < 8; i++)
                #pragma unroll
                for (int j = 0; j < 8; j++) {
                    cr[i][j] += ar[i]*bre[j] - ai[i]*bim[j];
                    ci[i][j] += ar[i]*bim[j] + ai[i]*bre[j];
                }
        }
    }

    #pragma unroll
    for (int i = 0; i < 8; i++) {
        size_t m = (size_t)(bm + ty*8 + i);
        #pragma unroll
        for (int j = 0; j < 8; j++) {
            int n = bn + tx*8 + j;
            outre[m * EE + n] = cr[i][j] + obr[n];
            outim[m * EE + n] = ci[i][j] + obi[n];
        }
    }
}

// ---------------- launch ----------------
extern "C" void kernel_launch(void* const* d_in, const int* in_sizes, int n_in,
                              void* d_out, int out_size)
{
    const float* xr  = (const float*)d_in[0];
    const float* xi  = (const float*)d_in[1];
    const float* wr  = (const float*)d_in[2];
    const float* wi  = (const float*)d_in[3];
    const float* br  = (const float*)d_in[4];
    const float* bi  = (const float*)d_in[5];
    const float* owr = (const float*)d_in[6];
    const float* owi = (const float*)d_in[7];
    const float* obr = (const float*)d_in[8];
    const float* obi = (const float*)d_in[9];
    float* out = (float*)d_out;

    k_init<<<1, 1>>>();
    k_proj<<<dim3(24, 32), 256>>>(xr, xi, wr, wi, br, bi);
    k_qk<<<dim3(8, 8, 64), 256>>>();
    k_scale<<<1, 1>>>();
    k_av<<<dim3(8, 64), 256>>>();
    k_avg<<<16384, 256>>>(out + 2 * (size_t)SEG);
    k_oproj<<<dim3(8, 32), 256>>>(owr, owi, obr, obi, out, out + SEG);
}